// round 2
// baseline (speedup 1.0000x reference)
#include <cuda_runtime.h>

// LnLstm: folded-weight formulation.
//   z_g[n,s,m] = sum_i mod[n,s,i] * Wc[g,s,m,i] + bc[g,s,m]
//   Wc = Wgate[:, :, :M] @ Wx   (per stream, per gate)
//   bc = b_gate + Wgate[:, :, :M] @ bx + Wgate[:, :, M:] @ h0
//   c = f*c0 + i*g ; h = o*tanh(c)

#define NS 8      // streams
#define NI 64     // inputs per stream (K of main GEMM)
#define NM 256    // features per stream

typedef unsigned long long ull;

// Scratch (device globals; no allocation in kernel_launch).
// g_WcT layout: [s][half][i(64)][col(512)], col = ml*4 + g  (ml = m & 127)
__device__ float g_WcT[NS * 2 * 64 * 512];
// g_bc layout: [s][m][g]
__device__ float g_bc[NS * NM * 4];

// ---------------------------------------------------------------------------
// Fold weights: Wc[g,s,m,i] = sum_{k<256} Wgate[s,m,k] * Wx[s,k,i]
// grid: (32 mtiles, 8 s), block 256 (t -> g = t>>6, i = t&63), 8 m per block.
// ---------------------------------------------------------------------------
__global__ void fold_weights_kernel(const float* __restrict__ Wx,
                                    const float* __restrict__ Wi,
                                    const float* __restrict__ Wf,
                                    const float* __restrict__ Wg,
                                    const float* __restrict__ Wo) {
    __shared__ float sWx[64 * 64];      // [kk][i]
    __shared__ float sWg[8][4][64];     // [mm][g][kk]

    const int t  = threadIdx.x;
    const int s  = blockIdx.y;
    const int m0 = blockIdx.x * 8;
    const int g  = t >> 6;
    const int i  = t & 63;

    const float* Wgates[4] = {Wi, Wf, Wg, Wo};
    const float* Wgp = Wgates[g];

    float acc[8];
#pragma unroll
    for (int mm = 0; mm < 8; mm++) acc[mm] = 0.f;

    for (int kc = 0; kc < 4; kc++) {
        // stage Wx chunk [kc*64 .. kc*64+63][0..63] (straight copy)
        const float* src = Wx + (s * 256 + kc * 64) * 64;
#pragma unroll
        for (int q = 0; q < 16; q++) sWx[t + 256 * q] = src[t + 256 * q];
        // stage gate rows: this thread loads kk = i for its gate g, all 8 mm
#pragma unroll
        for (int mm = 0; mm < 8; mm++)
            sWg[mm][g][i] = Wgp[(s * 256 + m0 + mm) * 512 + kc * 64 + i];
        __syncthreads();

#pragma unroll 8
        for (int kk = 0; kk < 64; kk++) {
            float xk = sWx[kk * 64 + i];
#pragma unroll
            for (int mm = 0; mm < 8; mm++) acc[mm] += sWg[mm][g][kk] * xk;
        }
        __syncthreads();
    }

#pragma unroll
    for (int mm = 0; mm < 8; mm++) {
        int m = m0 + mm;
        int half = m >> 7;
        int ml = m & 127;
        g_WcT[((s * 2 + half) * 64 + i) * 512 + ml * 4 + g] = acc[mm];
    }
}

// ---------------------------------------------------------------------------
// Fold biases: bc[s,m,g] = b_g[s,m] + sum_{k<256} Wg[s,m,k]*bx[s,k]
//                                   + sum_{k<256} Wg[s,m,256+k]*h0[s,k]
// grid: (4 g, 8 s), block 256 (m)
// ---------------------------------------------------------------------------
__global__ void fold_bias_kernel(const float* __restrict__ h0,
                                 const float* __restrict__ bx,
                                 const float* __restrict__ Wi,
                                 const float* __restrict__ Wf,
                                 const float* __restrict__ Wg,
                                 const float* __restrict__ Wo,
                                 const float* __restrict__ bi,
                                 const float* __restrict__ bf,
                                 const float* __restrict__ bg,
                                 const float* __restrict__ bo) {
    __shared__ float sXH[512];
    const int g = blockIdx.x, s = blockIdx.y, m = threadIdx.x;
    const float* Wgates[4] = {Wi, Wf, Wg, Wo};
    const float* bgates[4] = {bi, bf, bg, bo};

    sXH[m]       = bx[s * 256 + m];
    sXH[256 + m] = h0[s * 256 + m];
    __syncthreads();

    const float* wrow = Wgates[g] + (size_t)(s * 256 + m) * 512;
    float acc = bgates[g][s * 256 + m];
#pragma unroll 8
    for (int k = 0; k < 512; k++) acc += wrow[k] * sXH[k];
    g_bc[(s * 256 + m) * 4 + g] = acc;
}

// ---------------------------------------------------------------------------
// Main kernel: per CTA = (n-tile of 64 rows, half of m (128), stream s)
//   GEMM [64 rows, 512 cols, K=64] with packed f32x2 FMA + gate epilogue.
//   cols c = ml*4 + g ; col-pairs p: even p -> gates (i,f), odd p -> (g,o)
//   thread map: tx = t&63 handles pairs {tx, tx+64, tx+128, tx+192};
//               ty = t>>6 handles rows ty*8 .. ty*8+7
// ---------------------------------------------------------------------------
__device__ __forceinline__ void ffma2(ull& d, ull a, ull b) {
    asm("fma.rn.f32x2 %0, %1, %2, %0;" : "+l"(d) : "l"(a), "l"(b));
}
__device__ __forceinline__ float flo(ull v) { return __uint_as_float((unsigned)v); }
__device__ __forceinline__ float fhi(ull v) { return __uint_as_float((unsigned)(v >> 32)); }
__device__ __forceinline__ float sigm(float x) { return 1.f / (1.f + __expf(-x)); }

#define SMEM_W_BYTES  (64 * 256 * 8)             // 131072: [k][256 col-pairs] as ull
#define SMEM_M_BYTES  (64 * 65 * 8)              // 33280:  [k][65 padded rows] dup-f32x2
#define SMEM_TOTAL    (SMEM_W_BYTES + SMEM_M_BYTES + 512 * 4 + 128 * 4)  // 166912

__global__ __launch_bounds__(512, 1) void lstm_main_kernel(
    const float* __restrict__ mod, const float* __restrict__ c0,
    float* __restrict__ out, int n_total) {
    extern __shared__ char smem[];
    ull*   sW  = (ull*)smem;                                   // [k][p]
    ull*   sM  = (ull*)(smem + SMEM_W_BYTES);                  // [k][r] (stride 65)
    float* sB  = (float*)(smem + SMEM_W_BYTES + SMEM_M_BYTES); // 512
    float* sC0 = sB + 512;                                     // 128

    const int t    = threadIdx.x;
    const int n0   = blockIdx.x * 64;
    const int half = blockIdx.y;
    const int s    = blockIdx.z;

    // --- stage folded weights (straight float4 copy, 128 KB) ---
    {
        const float4* wsrc = (const float4*)(g_WcT + (size_t)(s * 2 + half) * 64 * 512);
        float4* wdst = (float4*)sW;
#pragma unroll
        for (int q = 0; q < 16; q++) wdst[t + 512 * q] = wsrc[t + 512 * q];
    }
    // --- stage mod tile, duplicated + transposed: sM[k][r] = {v,v} ---
    {
        const int k = t & 63, rb = t >> 6;
#pragma unroll
        for (int q = 0; q < 8; q++) {
            int r = rb + 8 * q;
            float v = mod[(size_t)(n0 + r) * 512 + s * 64 + k];
            ((float2*)sM)[k * 65 + r] = make_float2(v, v);
        }
    }
    // --- stage folded biases (contiguous 512) and c0 slice ---
    sB[t] = g_bc[(size_t)(s * 256 + half * 128) * 4 + t];
    if (t < 128) sC0[t] = c0[s * 256 + half * 128 + t];
    __syncthreads();

    const int tx = t & 63, ty = t >> 6;
    ull acc[8][4];
#pragma unroll
    for (int rr = 0; rr < 8; rr++)
#pragma unroll
        for (int j = 0; j < 4; j++) acc[rr][j] = 0ULL;

    const ull* wbase = sW + tx;
    const ull* mbase = sM + ty * 8;

#pragma unroll 4
    for (int k = 0; k < 64; k++) {
        ull w0 = wbase[k * 256];
        ull w1 = wbase[k * 256 + 64];
        ull w2 = wbase[k * 256 + 128];
        ull w3 = wbase[k * 256 + 192];
#pragma unroll
        for (int rr = 0; rr < 8; rr++) {
            ull a = mbase[k * 65 + rr];
            ffma2(acc[rr][0], a, w0);
            ffma2(acc[rr][1], a, w1);
            ffma2(acc[rr][2], a, w2);
            ffma2(acc[rr][3], a, w3);
        }
    }

    // --- epilogue: even lane holds (z_i, z_f), odd lane (z_g, z_o), same ml ---
#pragma unroll
    for (int j = 0; j < 4; j++) {
        const int p  = tx + 64 * j;
        const int ml = p >> 1;
        const float bi_ = sB[ml * 4 + 0], bf_ = sB[ml * 4 + 1];
        const float bg_ = sB[ml * 4 + 2], bo_ = sB[ml * 4 + 3];
        const float c0v = sC0[ml];
#pragma unroll
        for (int rr = 0; rr < 8; rr++) {
            ull mine  = acc[rr][j];
            ull other = __shfl_xor_sync(0xffffffffu, mine, 1);
            float zi = flo(mine) + bi_;
            float zf = fhi(mine) + bf_;
            float zg = flo(other) + bg_;
            float zo = fhi(other) + bo_;
            float iv = sigm(zi), fv = sigm(zf);
            float gv = tanhf(zg), ov = sigm(zo);
            float cc = fv * c0v + iv * gv;
            float hv = ov * tanhf(cc);
            if ((tx & 1) == 0) {
                int n = n0 + ty * 8 + rr;
                if (n < n_total)
                    out[(size_t)n * 2048 + s * 256 + half * 128 + ml] = hv;
            }
        }
    }
}

// ---------------------------------------------------------------------------
extern "C" void kernel_launch(void* const* d_in, const int* in_sizes, int n_in,
                              void* d_out, int out_size) {
    const float* mod = (const float*)d_in[0];
    const float* h0  = (const float*)d_in[1];
    const float* c0  = (const float*)d_in[2];
    const float* Wx  = (const float*)d_in[3];
    const float* bx  = (const float*)d_in[4];
    const float* Wi  = (const float*)d_in[5];
    const float* bi  = (const float*)d_in[6];
    const float* Wf  = (const float*)d_in[7];
    const float* bf  = (const float*)d_in[8];
    const float* Wg  = (const float*)d_in[9];
    const float* bg  = (const float*)d_in[10];
    const float* Wo  = (const float*)d_in[11];
    const float* bo  = (const float*)d_in[12];
    float* out = (float*)d_out;

    const int n = in_sizes[0] / 512;   // 16384

    cudaFuncSetAttribute(lstm_main_kernel,
                         cudaFuncAttributeMaxDynamicSharedMemorySize, SMEM_TOTAL);

    fold_weights_kernel<<<dim3(32, 8), 256>>>(Wx, Wi, Wf, Wg, Wo);
    fold_bias_kernel<<<dim3(4, 8), 256>>>(h0, bx, Wi, Wf, Wg, Wo, bi, bf, bg, bo);
    lstm_main_kernel<<<dim3(n / 64, 2, 8), 512, SMEM_TOTAL>>>(mod, c0, out, n);
}

// round 3
// speedup vs baseline: 1.3557x; 1.3557x over previous
#include <cuda_runtime.h>
#include <cuda_bf16.h>

// LnLstm folded-weight formulation, tensor-core (mma.sync bf16 split-3) GEMM.
//   z_g[n,s,m] = sum_i mod[n,s,i] * Wc[g,s,m,i] + bc[g,s,m]
//   Wc = Wgate[:, :, :M] @ Wx ;  bc = b_gate + Wgate[:,:, :M]@bx + Wgate[:,:,M:]@h0
//   c = f*c0 + i*g ; h = o*tanh(c)
// Main GEMM per stream s: [N=16384, 1024(=m*4+g), K=64] in bf16 hi/lo split:
//   a*b ~= a_hi*b_hi + a_hi*b_lo + a_lo*b_hi   (residual ~2^-18)

typedef unsigned int u32;

// ---- device scratch (no allocations allowed) ----
__device__ float g_Wc[8 * 64 * 1024];     // [s][i(64)][c=m*4+g (1024)]
__device__ u32   g_Whi[8 * 32 * 1024];    // [s][kpair(32)][c] packed bf16x2 (k even, k odd)
__device__ u32   g_Wlo[8 * 32 * 1024];
__device__ float g_bc[8 * 256 * 4];       // [s][m][g]

// ---------------------------------------------------------------------------
// Fold weights: Wc[g,s,m,i] = sum_{k<256} Wgate[s,m,k] * Wx[s,k,i]
// grid (128 mtiles, 8 s), block 256 (g = t>>6, i = t&63), 2 m per block.
// ---------------------------------------------------------------------------
__global__ void fold_weights_kernel(const float* __restrict__ Wx,
                                    const float* __restrict__ Wi,
                                    const float* __restrict__ Wf,
                                    const float* __restrict__ Wg,
                                    const float* __restrict__ Wo) {
    __shared__ float sWx[64 * 64];     // [kk][i]
    __shared__ float sWg[2][4][64];    // [mm][g][kk]

    const int t  = threadIdx.x;
    const int s  = blockIdx.y;
    const int m0 = blockIdx.x * 2;
    const int g  = t >> 6;
    const int i  = t & 63;

    const float* Wgates[4] = {Wi, Wf, Wg, Wo};
    const float* Wgp = Wgates[g];

    float acc[2] = {0.f, 0.f};

    for (int kc = 0; kc < 4; kc++) {
        const float* src = Wx + (s * 256 + kc * 64) * 64;
#pragma unroll
        for (int q = 0; q < 16; q++) sWx[t + 256 * q] = src[t + 256 * q];
#pragma unroll
        for (int mm = 0; mm < 2; mm++)
            sWg[mm][g][i] = Wgp[(size_t)(s * 256 + m0 + mm) * 512 + kc * 64 + i];
        __syncthreads();

#pragma unroll 16
        for (int kk = 0; kk < 64; kk++) {
            float xk = sWx[kk * 64 + i];
            acc[0] += sWg[0][g][kk] * xk;
            acc[1] += sWg[1][g][kk] * xk;
        }
        __syncthreads();
    }

#pragma unroll
    for (int mm = 0; mm < 2; mm++)
        g_Wc[((size_t)s * 64 + i) * 1024 + (m0 + mm) * 4 + g] = acc[mm];
}

// ---------------------------------------------------------------------------
// Fold biases: bc[s,m,g]
// ---------------------------------------------------------------------------
__global__ void fold_bias_kernel(const float* __restrict__ h0,
                                 const float* __restrict__ bx,
                                 const float* __restrict__ Wi,
                                 const float* __restrict__ Wf,
                                 const float* __restrict__ Wg,
                                 const float* __restrict__ Wo,
                                 const float* __restrict__ bi,
                                 const float* __restrict__ bf,
                                 const float* __restrict__ bg,
                                 const float* __restrict__ bo) {
    __shared__ float sXH[512];
    const int g = blockIdx.x, s = blockIdx.y, m = threadIdx.x;
    const float* Wgates[4] = {Wi, Wf, Wg, Wo};
    const float* bgates[4] = {bi, bf, bg, bo};

    sXH[m]       = bx[s * 256 + m];
    sXH[256 + m] = h0[s * 256 + m];
    __syncthreads();

    const float* wrow = Wgates[g] + (size_t)(s * 256 + m) * 512;
    float acc = bgates[g][s * 256 + m];
#pragma unroll 8
    for (int k = 0; k < 512; k++) acc += wrow[k] * sXH[k];
    g_bc[(s * 256 + m) * 4 + g] = acc;
}

// ---------------------------------------------------------------------------
// Convert folded weights to packed bf16x2 hi/lo: g_Whi/g_Wlo[s][kp][c]
// ---------------------------------------------------------------------------
__global__ void convert_w_kernel() {
    const int idx = blockIdx.x * 256 + threadIdx.x;   // 8*32*1024 = 262144
    const int s  = idx >> 15;
    const int kp = (idx >> 10) & 31;
    const int c  = idx & 1023;
    float x0 = g_Wc[((size_t)s * 64 + 2 * kp) * 1024 + c];
    float x1 = g_Wc[((size_t)s * 64 + 2 * kp + 1) * 1024 + c];
    __nv_bfloat16 h0 = __float2bfloat16(x0);
    __nv_bfloat16 h1 = __float2bfloat16(x1);
    __nv_bfloat16 l0 = __float2bfloat16(x0 - __bfloat162float(h0));
    __nv_bfloat16 l1 = __float2bfloat16(x1 - __bfloat162float(h1));
    __nv_bfloat162 hp = __halves2bfloat162(h0, h1);
    __nv_bfloat162 lp = __halves2bfloat162(l0, l1);
    g_Whi[idx] = *(u32*)&hp;
    g_Wlo[idx] = *(u32*)&lp;
}

// ---------------------------------------------------------------------------
// Main kernel: CTA = 128 rows x 128 cols (= 32 m x 4 gates), K=64 resident.
// 8 warps: wr = w>>1 (rows wr*32..+31), wc = w&1 (cols wc*64..+63).
// Warp tile 32x64: 2 m-tiles x 8 n-tiles of mma.m16n8k16, split-3 -> 192 mma.
// smem layout: packed bf16x2 over k-pairs, row stride 136 words (conflict-free:
// fragment lane addr = t4*136 + g8 -> bank t4*8+g8, all 32 distinct).
// ---------------------------------------------------------------------------
#define KSTRIDE 136
#define SMEM_MAIN ((4 * 32 * KSTRIDE) * 4 + 128 * 4 + 32 * 4)  // 70272 bytes

__device__ __forceinline__ void mma16816(float* d, const u32* a, u32 b0, u32 b1) {
    asm volatile(
        "mma.sync.aligned.m16n8k16.row.col.f32.bf16.bf16.f32 "
        "{%0,%1,%2,%3}, {%4,%5,%6,%7}, {%8,%9}, {%0,%1,%2,%3};"
        : "+f"(d[0]), "+f"(d[1]), "+f"(d[2]), "+f"(d[3])
        : "r"(a[0]), "r"(a[1]), "r"(a[2]), "r"(a[3]), "r"(b0), "r"(b1));
}
__device__ __forceinline__ float sigm(float x) { return 1.f / (1.f + __expf(-x)); }

__global__ __launch_bounds__(256, 2) void lstm_mma_kernel(
    const float* __restrict__ mod, const float* __restrict__ c0,
    float* __restrict__ out) {
    extern __shared__ u32 smem_u[];
    u32* sAhi = smem_u;                    // [kp][row], stride 136
    u32* sAlo = sAhi + 32 * KSTRIDE;
    u32* sBhi = sAlo + 32 * KSTRIDE;       // [kp][c], stride 136
    u32* sBlo = sBhi + 32 * KSTRIDE;
    float* sBc = (float*)(sBlo + 32 * KSTRIDE);   // 128: [m][g]
    float* sC0 = sBc + 128;                        // 32
    float* sH  = (float*)smem_u;           // reused post-compute: [row][m] stride 36

    const int t = threadIdx.x;
    const int s = blockIdx.x >> 3, ctile = blockIdx.x & 7;
    const int n0 = blockIdx.y * 128;

    // --- stage A (mod tile), fp32 -> bf16 hi/lo split, transposed to [kp][row]
    {
        const float* msrc = mod + (size_t)n0 * 512 + s * 64;
#pragma unroll
        for (int q = 0; q < 16; q++) {
            int idx = t + 256 * q;
            int row = idx >> 5, kp = idx & 31;
            float2 v = *(const float2*)(msrc + (size_t)row * 512 + kp * 2);
            __nv_bfloat16 hx = __float2bfloat16(v.x);
            __nv_bfloat16 hy = __float2bfloat16(v.y);
            __nv_bfloat16 lx = __float2bfloat16(v.x - __bfloat162float(hx));
            __nv_bfloat16 ly = __float2bfloat16(v.y - __bfloat162float(hy));
            __nv_bfloat162 hp = __halves2bfloat162(hx, hy);
            __nv_bfloat162 lp = __halves2bfloat162(lx, ly);
            sAhi[kp * KSTRIDE + row] = *(u32*)&hp;
            sAlo[kp * KSTRIDE + row] = *(u32*)&lp;
        }
    }
    // --- stage B (weights slice, already packed bf16x2) ---
    {
        const u32* hs = g_Whi + (size_t)s * 32 * 1024 + ctile * 128;
        const u32* ls = g_Wlo + (size_t)s * 32 * 1024 + ctile * 128;
#pragma unroll
        for (int q = 0; q < 16; q++) {
            int idx = t + 256 * q;
            int kp = idx >> 7, c = idx & 127;
            sBhi[kp * KSTRIDE + c] = hs[(size_t)kp * 1024 + c];
            sBlo[kp * KSTRIDE + c] = ls[(size_t)kp * 1024 + c];
        }
    }
    if (t < 128) sBc[t] = g_bc[((size_t)s * 256 + ctile * 32) * 4 + t];
    if (t < 32)  sC0[t] = c0[s * 256 + ctile * 32 + t];
    __syncthreads();

    const int lane = t & 31, w = t >> 5;
    const int wr = w >> 1, wc = w & 1;
    const int g8 = lane >> 2, t4 = lane & 3;
    const int r0 = wr * 32, cb = wc * 64;

    float acc[2][8][4];
#pragma unroll
    for (int mt = 0; mt < 2; mt++)
#pragma unroll
        for (int nt = 0; nt < 8; nt++)
#pragma unroll
            for (int j = 0; j < 4; j++) acc[mt][nt][j] = 0.f;

#pragma unroll
    for (int kc = 0; kc < 4; kc++) {
        const int k0 = kc * 8 + t4, k1 = kc * 8 + 4 + t4;
        u32 ah[2][4], al[2][4];
#pragma unroll
        for (int mt = 0; mt < 2; mt++) {
            int rb = r0 + mt * 16 + g8;
            ah[mt][0] = sAhi[k0 * KSTRIDE + rb];
            ah[mt][1] = sAhi[k0 * KSTRIDE + rb + 8];
            ah[mt][2] = sAhi[k1 * KSTRIDE + rb];
            ah[mt][3] = sAhi[k1 * KSTRIDE + rb + 8];
            al[mt][0] = sAlo[k0 * KSTRIDE + rb];
            al[mt][1] = sAlo[k0 * KSTRIDE + rb + 8];
            al[mt][2] = sAlo[k1 * KSTRIDE + rb];
            al[mt][3] = sAlo[k1 * KSTRIDE + rb + 8];
        }
#pragma unroll
        for (int nt = 0; nt < 8; nt++) {
            int cn = cb + nt * 8 + g8;
            u32 bh0 = sBhi[k0 * KSTRIDE + cn];
            u32 bh1 = sBhi[k1 * KSTRIDE + cn];
            u32 bl0 = sBlo[k0 * KSTRIDE + cn];
            u32 bl1 = sBlo[k1 * KSTRIDE + cn];
#pragma unroll
            for (int mt = 0; mt < 2; mt++) {
                mma16816(acc[mt][nt], ah[mt], bh0, bh1);   // hi*hi
                mma16816(acc[mt][nt], ah[mt], bl0, bl1);   // hi*lo
                mma16816(acc[mt][nt], al[mt], bh0, bh1);   // lo*hi
            }
        }
    }

    __syncthreads();   // done reading sA/sB; sH aliases sA region

    // --- epilogue: even-t4 lanes hold (z_i,z_f); odd hold (z_g,z_o). shfl pair.
#pragma unroll
    for (int mt = 0; mt < 2; mt++) {
#pragma unroll
        for (int nt = 0; nt < 8; nt++) {
            float a0 = acc[mt][nt][0], a1 = acc[mt][nt][1];
            float a2 = acc[mt][nt][2], a3 = acc[mt][nt][3];
            float o0 = __shfl_xor_sync(0xffffffffu, a0, 1);
            float o1 = __shfl_xor_sync(0xffffffffu, a1, 1);
            float o2 = __shfl_xor_sync(0xffffffffu, a2, 1);
            float o3 = __shfl_xor_sync(0xffffffffu, a3, 1);
            if ((t4 & 1) == 0) {
                int m = wc * 16 + nt * 2 + (t4 >> 1);
                float bi_ = sBc[m * 4 + 0], bf_ = sBc[m * 4 + 1];
                float bg_ = sBc[m * 4 + 2], bo_ = sBc[m * 4 + 3];
                float c0v = sC0[m];
                {   // rows r0 + mt*16 + g8
                    float iv = sigm(a0 + bi_), fv = sigm(a1 + bf_);
                    float gv = tanhf(o0 + bg_), ov = sigm(o1 + bo_);
                    float cc = fv * c0v + iv * gv;
                    sH[(r0 + mt * 16 + g8) * 36 + m] = ov * tanhf(cc);
                }
                {   // rows +8
                    float iv = sigm(a2 + bi_), fv = sigm(a3 + bf_);
                    float gv = tanhf(o2 + bg_), ov = sigm(o3 + bo_);
                    float cc = fv * c0v + iv * gv;
                    sH[(r0 + mt * 16 + 8 + g8) * 36 + m] = ov * tanhf(cc);
                }
            }
        }
    }
    __syncthreads();

    // --- coalesced writeout: 128 rows x 32 floats ---
    {
        int row = t >> 1, half = t & 1;
        float* orow = out + (size_t)(n0 + row) * 2048 + s * 256 + ctile * 32 + half * 16;
        const float4* hrow = (const float4*)(sH + row * 36 + half * 16);
#pragma unroll
        for (int j = 0; j < 4; j++) ((float4*)orow)[j] = hrow[j];
    }
}

// ---------------------------------------------------------------------------
extern "C" void kernel_launch(void* const* d_in, const int* in_sizes, int n_in,
                              void* d_out, int out_size) {
    const float* mod = (const float*)d_in[0];
    const float* h0  = (const float*)d_in[1];
    const float* c0  = (const float*)d_in[2];
    const float* Wx  = (const float*)d_in[3];
    const float* bx  = (const float*)d_in[4];
    const float* Wi  = (const float*)d_in[5];
    const float* bi  = (const float*)d_in[6];
    const float* Wf  = (const float*)d_in[7];
    const float* bf  = (const float*)d_in[8];
    const float* Wg  = (const float*)d_in[9];
    const float* bg  = (const float*)d_in[10];
    const float* Wo  = (const float*)d_in[11];
    const float* bo  = (const float*)d_in[12];
    float* out = (float*)d_out;

    const int n = in_sizes[0] / 512;   // 16384

    cudaFuncSetAttribute(lstm_mma_kernel,
                         cudaFuncAttributeMaxDynamicSharedMemorySize, SMEM_MAIN);

    fold_weights_kernel<<<dim3(128, 8), 256>>>(Wx, Wi, Wf, Wg, Wo);
    fold_bias_kernel<<<dim3(4, 8), 256>>>(h0, bx, Wi, Wf, Wg, Wo, bi, bf, bg, bo);
    convert_w_kernel<<<1024, 256>>>();
    lstm_mma_kernel<<<dim3(64, n / 128), 256, SMEM_MAIN>>>(mod, c0, out);
}

// round 5
// speedup vs baseline: 1.4343x; 1.0579x over previous
#include <cuda_runtime.h>
#include <cuda_bf16.h>
#include <cstdint>

// LnLstm folded-weight formulation, mma.sync (ldmatrix-fed) bf16 split-3 GEMM.
//   z_g[n,s,m] = sum_i mod[n,s,i] * Wc[g,s,m,i] + bc[g,s,m]
//   Wc = Wgate[:, :, :M] @ Wx ;  bc = b_gate + Wgate[:,:, :M]@bx + Wgate[:,:,M:]@h0
//   c = f*c0 + i*g ; h = o*tanh(c)
// Main GEMM per (s, ntile): D[128 rows, 1024 cols] = A[128,64] * B[1024,64]^T
// processed as 8 ctiles of 128 cols; bf16 split-3: a*b ~= ah*bh + ah*bl + al*bh.

typedef unsigned int u32;

// ---- device scratch ----
// g_Wsw: prepacked SW128-swizzled smem tile images of folded weights (bf16):
//   [s][ctile(8)][half: hi=0,lo=1][4096 u32]; tile = [c_local(128)][k(64)] bf16
__device__ u32   g_Wsw[8 * 8 * 2 * 4096];
__device__ float g_bc[8 * 256 * 4];       // [s][m][g]

static __device__ __forceinline__ uint32_t swz128(uint32_t b) {
    return b ^ ((b >> 3) & 0x70);
}
__device__ __forceinline__ uint32_t smem_u32(const void* p) {
    uint32_t a;
    asm("{ .reg .u64 t; cvta.to.shared.u64 t, %1; cvt.u32.u64 %0, t; }" : "=r"(a) : "l"(p));
    return a;
}
__device__ __forceinline__ float sigm(float x) { return 1.f / (1.f + __expf(-x)); }

__device__ __forceinline__ void ldsm4(u32* r, uint32_t addr) {
    asm volatile("ldmatrix.sync.aligned.m8n8.x4.shared.b16 {%0,%1,%2,%3}, [%4];"
                 : "=r"(r[0]), "=r"(r[1]), "=r"(r[2]), "=r"(r[3]) : "r"(addr));
}
__device__ __forceinline__ void mma16816(float* d, const u32* a, u32 b0, u32 b1) {
    asm volatile(
        "mma.sync.aligned.m16n8k16.row.col.f32.bf16.bf16.f32 "
        "{%0,%1,%2,%3}, {%4,%5,%6,%7}, {%8,%9}, {%0,%1,%2,%3};"
        : "+f"(d[0]), "+f"(d[1]), "+f"(d[2]), "+f"(d[3])
        : "r"(a[0]), "r"(a[1]), "r"(a[2]), "r"(a[3]), "r"(b0), "r"(b1));
}

// ---------------------------------------------------------------------------
// Fold weights: Wc[c= m*4+g][i] = sum_k Wgate[s,m,k]*Wx[s,k,i], pack bf16 hi/lo
// swizzled into g_Wsw. grid (16 c-tiles of 64, 8 s), block 256.
// Thread computes 4c x 4i outputs, K=256 in 4 chunks of 64.
// ---------------------------------------------------------------------------
__global__ void fold_weights_kernel(const float* __restrict__ Wx,
                                    const float* __restrict__ Wi,
                                    const float* __restrict__ Wf,
                                    const float* __restrict__ Wg,
                                    const float* __restrict__ Wo) {
    __shared__ float sWx[64 * 68];    // [kk][i]  (pad 68)
    __shared__ float sWgc[64 * 68];   // [kk][cl] (pad 68)

    const int t  = threadIdx.x;
    const int ct = blockIdx.x;        // 64-col tile
    const int s  = blockIdx.y;
    const float* Wgates[4] = {Wi, Wf, Wg, Wo};

    float acc[4][4];
#pragma unroll
    for (int a = 0; a < 4; a++)
#pragma unroll
        for (int b = 0; b < 4; b++) acc[a][b] = 0.f;

    const int i0  = (t & 15) * 4;
    const int cl0 = (t >> 4) * 4;

    for (int kc = 0; kc < 4; kc++) {
#pragma unroll
        for (int q = 0; q < 16; q++) {
            int idx = q * 256 + t;
            int kk = idx >> 6, i = idx & 63;
            sWx[kk * 68 + i] = Wx[(size_t)(s * 256 + kc * 64 + kk) * 64 + i];
        }
#pragma unroll
        for (int q = 0; q < 16; q++) {
            int idx = q * 256 + t;
            int cl = idx >> 6, kk = idx & 63;
            int c = ct * 64 + cl, m = c >> 2, g = c & 3;
            sWgc[kk * 68 + cl] = Wgates[g][(size_t)(s * 256 + m) * 512 + kc * 64 + kk];
        }
        __syncthreads();

#pragma unroll 8
        for (int kk = 0; kk < 64; kk++) {
            float4 xv = *(const float4*)&sWx[kk * 68 + i0];
            float4 gv = *(const float4*)&sWgc[kk * 68 + cl0];
            const float* xp = (const float*)&xv;
            const float* gp = (const float*)&gv;
#pragma unroll
            for (int a = 0; a < 4; a++)
#pragma unroll
                for (int b = 0; b < 4; b++) acc[a][b] += gp[a] * xp[b];
        }
        __syncthreads();
    }

#pragma unroll
    for (int a = 0; a < 4; a++) {
        int c = ct * 64 + cl0 + a;
        int ct128 = c >> 7, cl128 = c & 127;
        char* base = (char*)(g_Wsw + (size_t)((s * 8 + ct128) * 2) * 4096);
#pragma unroll
        for (int b = 0; b < 4; b++) {
            float x = acc[a][b];
            __nv_bfloat16 hb = __float2bfloat16(x);
            __nv_bfloat16 lb = __float2bfloat16(x - __bfloat162float(hb));
            uint32_t sw = swz128((uint32_t)(cl128 * 128 + (i0 + b) * 2));
            *(unsigned short*)(base + sw)         = *(unsigned short*)&hb;
            *(unsigned short*)(base + 16384 + sw) = *(unsigned short*)&lb;
        }
    }
}

// ---------------------------------------------------------------------------
// Fold biases: bc[s,m,g] = b_g + Wg[:, :256]@bx + Wg[:, 256:]@h0
// grid (4 g, 8 s, 8 mchunk), block 256 (32 m x 8 k-slices), smem reduce.
// ---------------------------------------------------------------------------
__global__ void fold_bias_kernel(const float* __restrict__ h0,
                                 const float* __restrict__ bx,
                                 const float* __restrict__ Wi,
                                 const float* __restrict__ Wf,
                                 const float* __restrict__ Wg,
                                 const float* __restrict__ Wo,
                                 const float* __restrict__ bi,
                                 const float* __restrict__ bf,
                                 const float* __restrict__ bg,
                                 const float* __restrict__ bo) {
    __shared__ float sXH[512];
    __shared__ float red[256];
    const int g = blockIdx.x, s = blockIdx.y, mc = blockIdx.z;
    const int t = threadIdx.x;
    const float* Wgates[4] = {Wi, Wf, Wg, Wo};
    const float* bgates[4] = {bi, bf, bg, bo};

    sXH[t]       = bx[s * 256 + t];
    sXH[256 + t] = h0[s * 256 + t];
    __syncthreads();

    const int ml = t >> 3, ks = t & 7;
    const int m = mc * 32 + ml;
    const float* wrow = Wgates[g] + (size_t)(s * 256 + m) * 512 + ks * 64;
    float a = 0.f;
#pragma unroll 8
    for (int kk = 0; kk < 64; kk++) a += wrow[kk] * sXH[ks * 64 + kk];
    red[t] = a;
    __syncthreads();
    if (t < 32) {
        float v = 0.f;
#pragma unroll
        for (int j = 0; j < 8; j++) v += red[t * 8 + j];
        v += bgates[g][s * 256 + mc * 32 + t];
        g_bc[(s * 256 + mc * 32 + t) * 4 + g] = v;
    }
}

// ---------------------------------------------------------------------------
// Main kernel: CTA = (s, 128-row n-tile), loops 8 ctiles of 128 cols.
// 256 threads, 8 warps: warp tile 32 rows x 64 cols; fragments via ldmatrix.
// smem: bias[1024f]@0, c0[256f]@4096, pad, A hi@8192, A lo@24576,
//       B hi@40960, B lo@57344; sH aliases B hi region in epilogue.
// ---------------------------------------------------------------------------
#define OFF_C0   4096
#define OFF_AHI  8192
#define OFF_ALO  24576
#define OFF_BHI  40960
#define OFF_BLO  57344
#define SMEM_MAIN 73728

__global__ __launch_bounds__(256, 2) void lstm_mma_kernel(
    const float* __restrict__ mod, const float* __restrict__ c0,
    float* __restrict__ out) {
    extern __shared__ char smem[];
    const uint32_t sbase = smem_u32(smem);
    float* sBc = (float*)smem;                 // [m(256)][g(4)]
    float* sC0 = (float*)(smem + OFF_C0);      // [m(256)]

    const int t = threadIdx.x;
    const int w = t >> 5, lane = t & 31;
    const int s = blockIdx.x;
    const int n0 = blockIdx.y * 128;

    // --- stage A once: fp32 -> bf16 hi/lo, swizzled [row][k] ---
    {
        const float* msrc = mod + (size_t)n0 * 512 + s * 64;
#pragma unroll
        for (int q = 0; q < 16; q++) {
            int idx = q * 256 + t;
            int row = idx >> 5, kp = idx & 31;
            float2 v = *(const float2*)(msrc + (size_t)row * 512 + kp * 2);
            __nv_bfloat16 hx = __float2bfloat16(v.x);
            __nv_bfloat16 hy = __float2bfloat16(v.y);
            __nv_bfloat16 lx = __float2bfloat16(v.x - __bfloat162float(hx));
            __nv_bfloat16 ly = __float2bfloat16(v.y - __bfloat162float(hy));
            __nv_bfloat162 hp = __halves2bfloat162(hx, hy);
            __nv_bfloat162 lp = __halves2bfloat162(lx, ly);
            uint32_t sw = swz128((uint32_t)(row * 128 + kp * 4));
            *(u32*)(smem + OFF_AHI + sw) = *(u32*)&hp;
            *(u32*)(smem + OFF_ALO + sw) = *(u32*)&lp;
        }
    }
#pragma unroll
    for (int q = 0; q < 4; q++) sBc[q * 256 + t] = g_bc[(size_t)s * 1024 + q * 256 + t];
    sC0[t] = c0[s * 256 + t];

    // --- per-lane ldmatrix address precompute ---
    const int wr = w >> 1, wc = w & 1;
    const int r0 = wr * 32, cb = wc * 64;
    const uint32_t X   = (lane & 7) << 4;
    const uint32_t kaA = ((lane >> 4) & 1) * 16;
    const uint32_t kaB = ((lane >> 3) & 1) * 16;
    const uint32_t aoff = sbase + OFF_AHI + (uint32_t)(r0 + (lane & 15)) * 128;
    const uint32_t boff = sbase + OFF_BHI +
                          (uint32_t)(cb + ((lane >> 4) & 1) * 8 + (lane & 7)) * 128;

    const int q4 = lane & 3, gr = lane >> 2;

#pragma unroll 1
    for (int ct = 0; ct < 8; ct++) {
        // --- stage B tile (prepacked swizzled images, straight float4 copy) ---
        {
            const float4* bh = (const float4*)(g_Wsw + (size_t)((s * 8 + ct) * 2) * 4096);
            const float4* bl = bh + 1024;
            float4* dh = (float4*)(smem + OFF_BHI);
            float4* dl = (float4*)(smem + OFF_BLO);
#pragma unroll
            for (int q = 0; q < 4; q++) {
                dh[q * 256 + t] = bh[q * 256 + t];
                dl[q * 256 + t] = bl[q * 256 + t];
            }
        }
        __syncthreads();

        float acc[2][8][4];
#pragma unroll
        for (int mt = 0; mt < 2; mt++)
#pragma unroll
            for (int nt = 0; nt < 8; nt++)
#pragma unroll
                for (int j = 0; j < 4; j++) acc[mt][nt][j] = 0.f;

#pragma unroll
        for (int kc = 0; kc < 4; kc++) {
            const uint32_t koA = (kc * 32 + kaA) ^ X;
            const uint32_t koB = (kc * 32 + kaB) ^ X;
            u32 ah0[4], ah1[4], al0[4], al1[4];
            ldsm4(ah0, aoff + koA);
            ldsm4(ah1, aoff + 2048 + koA);
            ldsm4(al0, aoff + 16384 + koA);
            ldsm4(al1, aoff + 16384 + 2048 + koA);
#pragma unroll
            for (int ntp = 0; ntp < 4; ntp++) {
                u32 bh[4], bl[4];
                ldsm4(bh, boff + ntp * 2048 + koB);
                ldsm4(bl, boff + 16384 + ntp * 2048 + koB);
                const int nt0 = ntp * 2, nt1 = ntp * 2 + 1;
                mma16816(acc[0][nt0], ah0, bh[0], bh[1]);
                mma16816(acc[0][nt0], al0, bh[0], bh[1]);
                mma16816(acc[0][nt0], ah0, bl[0], bl[1]);
                mma16816(acc[1][nt0], ah1, bh[0], bh[1]);
                mma16816(acc[1][nt0], al1, bh[0], bh[1]);
                mma16816(acc[1][nt0], ah1, bl[0], bl[1]);
                mma16816(acc[0][nt1], ah0, bh[2], bh[3]);
                mma16816(acc[0][nt1], al0, bh[2], bh[3]);
                mma16816(acc[0][nt1], ah0, bl[2], bl[3]);
                mma16816(acc[1][nt1], ah1, bh[2], bh[3]);
                mma16816(acc[1][nt1], al1, bh[2], bh[3]);
                mma16816(acc[1][nt1], ah1, bl[2], bl[3]);
            }
        }
        __syncthreads();   // B reads done; sH aliases B hi region

        // --- epilogue: gates + LSTM cell, staged to sH for coalesced write ---
        float* sH = (float*)(smem + OFF_BHI);   // [row][m] stride 36
#pragma unroll
        for (int mt = 0; mt < 2; mt++) {
#pragma unroll
            for (int nt = 0; nt < 8; nt++) {
                float a0 = acc[mt][nt][0], a1 = acc[mt][nt][1];
                float a2 = acc[mt][nt][2], a3 = acc[mt][nt][3];
                float o0 = __shfl_xor_sync(0xffffffffu, a0, 1);
                float o1 = __shfl_xor_sync(0xffffffffu, a1, 1);
                float o2 = __shfl_xor_sync(0xffffffffu, a2, 1);
                float o3 = __shfl_xor_sync(0xffffffffu, a3, 1);
                if ((q4 & 1) == 0) {
                    int mloc = wc * 16 + nt * 2 + (q4 >> 1);
                    int mg = ct * 32 + mloc;
                    float bi_ = sBc[mg * 4 + 0], bf_ = sBc[mg * 4 + 1];
                    float bg_ = sBc[mg * 4 + 2], bo_ = sBc[mg * 4 + 3];
                    float c0v = sC0[mg];
                    {
                        float iv = sigm(a0 + bi_), fv = sigm(a1 + bf_);
                        float gv = tanhf(o0 + bg_), ov = sigm(o1 + bo_);
                        float cc = fv * c0v + iv * gv;
                        sH[(r0 + mt * 16 + gr) * 36 + mloc] = ov * tanhf(cc);
                    }
                    {
                        float iv = sigm(a2 + bi_), fv = sigm(a3 + bf_);
                        float gv = tanhf(o2 + bg_), ov = sigm(o3 + bo_);
                        float cc = fv * c0v + iv * gv;
                        sH[(r0 + mt * 16 + 8 + gr) * 36 + mloc] = ov * tanhf(cc);
                    }
                }
            }
        }
        __syncthreads();

        // --- coalesced writeout: 128 rows x 32 floats ---
        {
            int row = t >> 1, half = t & 1;
            float* orow = out + (size_t)(n0 + row) * 2048 + s * 256 + ct * 32 + half * 16;
            const float* hrow = sH + row * 36 + half * 16;
#pragma unroll
            for (int j = 0; j < 4; j++)
                ((float4*)orow)[j] = ((const float4*)hrow)[j];
        }
        __syncthreads();   // sH dead before next B staging
    }
}

// ---------------------------------------------------------------------------
extern "C" void kernel_launch(void* const* d_in, const int* in_sizes, int n_in,
                              void* d_out, int out_size) {
    const float* mod = (const float*)d_in[0];
    const float* h0  = (const float*)d_in[1];
    const float* c0  = (const float*)d_in[2];
    const float* Wx  = (const float*)d_in[3];
    const float* bx  = (const float*)d_in[4];
    const float* Wi  = (const float*)d_in[5];
    const float* bi  = (const float*)d_in[6];
    const float* Wf  = (const float*)d_in[7];
    const float* bf  = (const float*)d_in[8];
    const float* Wg  = (const float*)d_in[9];
    const float* bg  = (const float*)d_in[10];
    const float* Wo  = (const float*)d_in[11];
    const float* bo  = (const float*)d_in[12];
    float* out = (float*)d_out;

    const int n = in_sizes[0] / 512;   // 16384

    cudaFuncSetAttribute(lstm_mma_kernel,
                         cudaFuncAttributeMaxDynamicSharedMemorySize, SMEM_MAIN);

    fold_weights_kernel<<<dim3(16, 8), 256>>>(Wx, Wi, Wf, Wg, Wo);
    fold_bias_kernel<<<dim3(4, 8, 8), 256>>>(h0, bx, Wi, Wf, Wg, Wo, bi, bf, bg, bo);
    lstm_mma_kernel<<<dim3(8, n / 128), 256, SMEM_MAIN>>>(mod, c0, out);
}

// round 8
// speedup vs baseline: 2.7715x; 1.9323x over previous
#include <cuda_runtime.h>
#include <cuda_bf16.h>
#include <cstdint>

// LnLstm folded-weight formulation, mma.sync (ldmatrix-fed) bf16 split-3 GEMM.
//   z_g[n,s,m] = sum_i mod[n,s,i] * Wc[g,s,m,i] + bc[g,s,m]
//   Wc = Wgate[:, :, :M] @ Wx ;  bc = b_gate + Wgate[:,:, :M]@bx + Wgate[:,:,M:]@h0
//   c = f*c0 + i*g ; h = o*tanh(c)
// Main GEMM per (s, ntile): D[128 rows, 1024 cols] = A[128,64] * B[1024,64]^T
// processed as 8 ctiles of 128 cols; bf16 split-3: a*b ~= ah*bh + ah*bl + al*bh.

typedef unsigned int u32;

// ---- device scratch ----
// g_Wsw: prepacked SW128-swizzled smem tile images of folded weights (bf16):
//   [s][ctile(8)][half: hi=0,lo=1][4096 u32]; tile = [c_local(128)][k(64)] bf16
__device__ u32   g_Wsw[8 * 8 * 2 * 4096];
__device__ float g_bc[8 * 256 * 4];       // [s][m][g]

static __device__ __forceinline__ uint32_t swz128(uint32_t b) {
    return b ^ ((b >> 3) & 0x70);
}
__device__ __forceinline__ uint32_t smem_u32(const void* p) {
    uint32_t a;
    asm("{ .reg .u64 t; cvta.to.shared.u64 t, %1; cvt.u32.u64 %0, t; }" : "=r"(a) : "l"(p));
    return a;
}
// fast activations: EX2/RCP based, err ~1e-6 (budget 1e-3)
__device__ __forceinline__ float fsig(float x) {
    return __fdividef(1.f, 1.f + __expf(-x));
}
__device__ __forceinline__ float ftanh(float x) {
    return 1.f - __fdividef(2.f, 1.f + __expf(2.f * x));
}

__device__ __forceinline__ void ldsm4(u32* r, uint32_t addr) {
    asm volatile("ldmatrix.sync.aligned.m8n8.x4.shared.b16 {%0,%1,%2,%3}, [%4];"
                 : "=r"(r[0]), "=r"(r[1]), "=r"(r[2]), "=r"(r[3]) : "r"(addr));
}
__device__ __forceinline__ void mma16816(float* d, const u32* a, u32 b0, u32 b1) {
    asm volatile(
        "mma.sync.aligned.m16n8k16.row.col.f32.bf16.bf16.f32 "
        "{%0,%1,%2,%3}, {%4,%5,%6,%7}, {%8,%9}, {%0,%1,%2,%3};"
        : "+f"(d[0]), "+f"(d[1]), "+f"(d[2]), "+f"(d[3])
        : "r"(a[0]), "r"(a[1]), "r"(a[2]), "r"(a[3]), "r"(b0), "r"(b1));
}

// ---------------------------------------------------------------------------
// Fold weights: Wc[c=m*4+g][i] = sum_k Wgate[s,m,k]*Wx[s,k,i]; pack bf16 hi/lo
// swizzled into g_Wsw. grid (16 ctile64, 8 s), block 512; thread = 2c x 4i.
// ---------------------------------------------------------------------------
__global__ __launch_bounds__(512) void fold_weights_kernel(
    const float* __restrict__ Wx,
    const float* __restrict__ Wi,
    const float* __restrict__ Wf,
    const float* __restrict__ Wg,
    const float* __restrict__ Wo) {
    __shared__ float sWx[64 * 68];    // [kk][i]
    __shared__ float sWgc[64 * 68];   // [cl][kk]

    const int t  = threadIdx.x;
    const int ct = blockIdx.x;
    const int s  = blockIdx.y;
    const float* Wgates[4] = {Wi, Wf, Wg, Wo};

    const int i0  = (t & 15) * 4;
    const int cl0 = (t >> 4) * 2;

    float acc[2][4];
#pragma unroll
    for (int a = 0; a < 2; a++)
#pragma unroll
        for (int b = 0; b < 4; b++) acc[a][b] = 0.f;

    for (int kc = 0; kc < 4; kc++) {
#pragma unroll
        for (int q = 0; q < 8; q++) {
            int idx = q * 512 + t;
            int kk = idx >> 6, i = idx & 63;
            sWx[kk * 68 + i] = Wx[(size_t)(s * 256 + kc * 64 + kk) * 64 + i];
        }
#pragma unroll
        for (int q = 0; q < 8; q++) {
            int idx = q * 512 + t;
            int cl = idx >> 6, kk = idx & 63;
            int c = ct * 64 + cl, m = c >> 2, g = c & 3;
            sWgc[cl * 68 + kk] = Wgates[g][(size_t)(s * 256 + m) * 512 + kc * 64 + kk];
        }
        __syncthreads();

#pragma unroll 8
        for (int kk = 0; kk < 64; kk++) {
            float4 xv = *(const float4*)&sWx[kk * 68 + i0];
            float g0 = sWgc[cl0 * 68 + kk];
            float g1 = sWgc[(cl0 + 1) * 68 + kk];
            const float* xp = (const float*)&xv;
#pragma unroll
            for (int b = 0; b < 4; b++) {
                acc[0][b] += g0 * xp[b];
                acc[1][b] += g1 * xp[b];
            }
        }
        __syncthreads();
    }

#pragma unroll
    for (int a = 0; a < 2; a++) {
        int c = ct * 64 + cl0 + a;
        int ct128 = c >> 7, cl128 = c & 127;
        char* base = (char*)(g_Wsw + (size_t)((s * 8 + ct128) * 2) * 4096);
#pragma unroll
        for (int b = 0; b < 4; b++) {
            float x = acc[a][b];
            __nv_bfloat16 hb = __float2bfloat16(x);
            __nv_bfloat16 lb = __float2bfloat16(x - __bfloat162float(hb));
            uint32_t sw = swz128((uint32_t)(cl128 * 128 + (i0 + b) * 2));
            *(unsigned short*)(base + sw)         = *(unsigned short*)&hb;
            *(unsigned short*)(base + 16384 + sw) = *(unsigned short*)&lb;
        }
    }
}

// ---------------------------------------------------------------------------
// Fold biases: bc[s,m,g] = b_g + Wg[:, :256]@bx + Wg[:, 256:]@h0
// grid (4 g, 8 s, 8 mchunk), block 256 (32 m x 8 k-slices), smem reduce.
// ---------------------------------------------------------------------------
__global__ void fold_bias_kernel(const float* __restrict__ h0,
                                 const float* __restrict__ bx,
                                 const float* __restrict__ Wi,
                                 const float* __restrict__ Wf,
                                 const float* __restrict__ Wg,
                                 const float* __restrict__ Wo,
                                 const float* __restrict__ bi,
                                 const float* __restrict__ bf,
                                 const float* __restrict__ bg,
                                 const float* __restrict__ bo) {
    __shared__ float sXH[512];
    __shared__ float red[256];
    const int g = blockIdx.x, s = blockIdx.y, mc = blockIdx.z;
    const int t = threadIdx.x;
    const float* Wgates[4] = {Wi, Wf, Wg, Wo};
    const float* bgates[4] = {bi, bf, bg, bo};

    sXH[t]       = bx[s * 256 + t];
    sXH[256 + t] = h0[s * 256 + t];
    __syncthreads();

    const int ml = t >> 3, ks = t & 7;
    const int m = mc * 32 + ml;
    const float* wrow = Wgates[g] + (size_t)(s * 256 + m) * 512 + ks * 64;
    float a = 0.f;
#pragma unroll 8
    for (int kk = 0; kk < 64; kk++) a += wrow[kk] * sXH[ks * 64 + kk];
    red[t] = a;
    __syncthreads();
    if (t < 32) {
        float v = 0.f;
#pragma unroll
        for (int j = 0; j < 8; j++) v += red[t * 8 + j];
        v += bgates[g][s * 256 + mc * 32 + t];
        g_bc[(s * 256 + mc * 32 + t) * 4 + g] = v;
    }
}

// ---------------------------------------------------------------------------
// Main kernel: CTA = (s, 128-row n-tile), loops 8 ctiles of 128 cols.
// 256 threads, 8 warps: warp tile 32 rows x 64 cols; fragments via ldmatrix.
// Epilogue: all 32 lanes active (even lane -> row r, odd lane -> row r+8).
// ---------------------------------------------------------------------------
#define OFF_C0   4096
#define OFF_AHI  8192
#define OFF_ALO  24576
#define OFF_BHI  40960
#define OFF_BLO  57344
#define SMEM_MAIN 73728

__global__ __launch_bounds__(256, 2) void lstm_mma_kernel(
    const float* __restrict__ mod, const float* __restrict__ c0,
    float* __restrict__ out) {
    extern __shared__ char smem[];
    const uint32_t sbase = smem_u32(smem);
    float* sBc = (float*)smem;                 // [m(256)][g(4)]
    float* sC0 = (float*)(smem + OFF_C0);      // [m(256)]

    const int t = threadIdx.x;
    const int w = t >> 5, lane = t & 31;
    const int s = blockIdx.x;
    const int n0 = blockIdx.y * 128;

    // --- stage A once: fp32 -> bf16 hi/lo, swizzled [row][k] ---
    {
        const float* msrc = mod + (size_t)n0 * 512 + s * 64;
#pragma unroll
        for (int q = 0; q < 16; q++) {
            int idx = q * 256 + t;
            int row = idx >> 5, kp = idx & 31;
            float2 v = *(const float2*)(msrc + (size_t)row * 512 + kp * 2);
            __nv_bfloat16 hx = __float2bfloat16(v.x);
            __nv_bfloat16 hy = __float2bfloat16(v.y);
            __nv_bfloat16 lx = __float2bfloat16(v.x - __bfloat162float(hx));
            __nv_bfloat16 ly = __float2bfloat16(v.y - __bfloat162float(hy));
            __nv_bfloat162 hp = __halves2bfloat162(hx, hy);
            __nv_bfloat162 lp = __halves2bfloat162(lx, ly);
            uint32_t sw = swz128((uint32_t)(row * 128 + kp * 4));
            *(u32*)(smem + OFF_AHI + sw) = *(u32*)&hp;
            *(u32*)(smem + OFF_ALO + sw) = *(u32*)&lp;
        }
    }
#pragma unroll
    for (int q = 0; q < 4; q++) sBc[q * 256 + t] = g_bc[(size_t)s * 1024 + q * 256 + t];
    sC0[t] = c0[s * 256 + t];

    // --- per-lane ldmatrix address precompute ---
    const int wr = w >> 1, wc = w & 1;
    const int r0 = wr * 32, cb = wc * 64;
    const uint32_t X   = (lane & 7) << 4;
    const uint32_t kaA = ((lane >> 4) & 1) * 16;
    const uint32_t kaB = ((lane >> 3) & 1) * 16;
    const uint32_t aoff = sbase + OFF_AHI + (uint32_t)(r0 + (lane & 15)) * 128;
    const uint32_t boff = sbase + OFF_BHI +
                          (uint32_t)(cb + ((lane >> 4) & 1) * 8 + (lane & 7)) * 128;

    const int q4 = lane & 3, gr = lane >> 2;

#pragma unroll 1
    for (int ct = 0; ct < 8; ct++) {
        // --- stage B tile (prepacked swizzled images, straight float4 copy) ---
        {
            const float4* bh = (const float4*)(g_Wsw + (size_t)((s * 8 + ct) * 2) * 4096);
            const float4* bl = bh + 1024;
            float4* dh = (float4*)(smem + OFF_BHI);
            float4* dl = (float4*)(smem + OFF_BLO);
#pragma unroll
            for (int q = 0; q < 4; q++) {
                dh[q * 256 + t] = bh[q * 256 + t];
                dl[q * 256 + t] = bl[q * 256 + t];
            }
        }
        __syncthreads();

        float acc[2][8][4];
#pragma unroll
        for (int mt = 0; mt < 2; mt++)
#pragma unroll
            for (int nt = 0; nt < 8; nt++)
#pragma unroll
                for (int j = 0; j < 4; j++) acc[mt][nt][j] = 0.f;

#pragma unroll
        for (int kc = 0; kc < 4; kc++) {
            const uint32_t koA = (kc * 32 + kaA) ^ X;
            const uint32_t koB = (kc * 32 + kaB) ^ X;
            u32 ah0[4], ah1[4], al0[4], al1[4];
            ldsm4(ah0, aoff + koA);
            ldsm4(ah1, aoff + 2048 + koA);
            ldsm4(al0, aoff + 16384 + koA);
            ldsm4(al1, aoff + 16384 + 2048 + koA);
#pragma unroll
            for (int ntp = 0; ntp < 4; ntp++) {
                u32 bh[4], bl[4];
                ldsm4(bh, boff + ntp * 2048 + koB);
                ldsm4(bl, boff + 16384 + ntp * 2048 + koB);
                const int nt0 = ntp * 2, nt1 = ntp * 2 + 1;
                mma16816(acc[0][nt0], ah0, bh[0], bh[1]);
                mma16816(acc[0][nt0], al0, bh[0], bh[1]);
                mma16816(acc[0][nt0], ah0, bl[0], bl[1]);
                mma16816(acc[1][nt0], ah1, bh[0], bh[1]);
                mma16816(acc[1][nt0], al1, bh[0], bh[1]);
                mma16816(acc[1][nt0], ah1, bl[0], bl[1]);
                mma16816(acc[0][nt1], ah0, bh[2], bh[3]);
                mma16816(acc[0][nt1], al0, bh[2], bh[3]);
                mma16816(acc[0][nt1], ah0, bl[2], bl[3]);
                mma16816(acc[1][nt1], ah1, bh[2], bh[3]);
                mma16816(acc[1][nt1], al1, bh[2], bh[3]);
                mma16816(acc[1][nt1], ah1, bl[2], bl[3]);
            }
        }
        __syncthreads();   // B reads done; sH aliases B hi region

        // --- epilogue: all lanes active; even lane -> row r, odd -> row r+8 ---
        float* sH = (float*)(smem + OFF_BHI);   // [row][m] stride 36
#pragma unroll
        for (int mt = 0; mt < 2; mt++) {
#pragma unroll
            for (int nt = 0; nt < 8; nt++) {
                float a0 = acc[mt][nt][0], a1 = acc[mt][nt][1];
                float a2 = acc[mt][nt][2], a3 = acc[mt][nt][3];
                float o0 = __shfl_xor_sync(0xffffffffu, a0, 1);
                float o1 = __shfl_xor_sync(0xffffffffu, a1, 1);
                float o2 = __shfl_xor_sync(0xffffffffu, a2, 1);
                float o3 = __shfl_xor_sync(0xffffffffu, a3, 1);
                float zi, zf, zg, zo;
                int rr;
                if ((q4 & 1) == 0) {   // even lane: row r, gates (i,f) own, (g,o) partner
                    zi = a0; zf = a1; zg = o0; zo = o1;
                    rr = r0 + mt * 16 + gr;
                } else {               // odd lane: row r+8, (i,f) partner, (g,o) own
                    zi = o2; zf = o3; zg = a2; zo = a3;
                    rr = r0 + mt * 16 + 8 + gr;
                }
                int mloc = wc * 16 + nt * 2 + (q4 >> 1);
                int mg = ct * 32 + mloc;
                float iv = fsig(zi + sBc[mg * 4 + 0]);
                float fv = fsig(zf + sBc[mg * 4 + 1]);
                float gv = ftanh(zg + sBc[mg * 4 + 2]);
                float ov = fsig(zo + sBc[mg * 4 + 3]);
                float cc = fv * sC0[mg] + iv * gv;
                sH[rr * 36 + mloc] = ov * ftanh(cc);
            }
        }
        __syncthreads();

        // --- coalesced writeout: 128 rows x 32 floats ---
        {
            int row = t >> 1, half = t & 1;
            float* orow = out + (size_t)(n0 + row) * 2048 + s * 256 + ct * 32 + half * 16;
            const float* hrow = sH + row * 36 + half * 16;
#pragma unroll
            for (int j = 0; j < 4; j++)
                ((float4*)orow)[j] = ((const float4*)hrow)[j];
        }
        __syncthreads();   // sH dead before next B staging
    }
}

// ---------------------------------------------------------------------------
extern "C" void kernel_launch(void* const* d_in, const int* in_sizes, int n_in,
                              void* d_out, int out_size) {
    const float* mod = (const float*)d_in[0];
    const float* h0  = (const float*)d_in[1];
    const float* c0  = (const float*)d_in[2];
    const float* Wx  = (const float*)d_in[3];
    const float* bx  = (const float*)d_in[4];
    const float* Wi  = (const float*)d_in[5];
    const float* bi  = (const float*)d_in[6];
    const float* Wf  = (const float*)d_in[7];
    const float* bf  = (const float*)d_in[8];
    const float* Wg  = (const float*)d_in[9];
    const float* bg  = (const float*)d_in[10];
    const float* Wo  = (const float*)d_in[11];
    const float* bo  = (const float*)d_in[12];
    float* out = (float*)d_out;

    const int n = in_sizes[0] / 512;   // 16384

    cudaFuncSetAttribute(lstm_mma_kernel,
                         cudaFuncAttributeMaxDynamicSharedMemorySize, SMEM_MAIN);

    fold_weights_kernel<<<dim3(16, 8), 512>>>(Wx, Wi, Wf, Wg, Wo);
    fold_bias_kernel<<<dim3(4, 8, 8), 256>>>(h0, bx, Wi, Wf, Wg, Wo, bi, bf, bg, bo);
    lstm_mma_kernel<<<dim3(8, n / 128), 256, SMEM_MAIN>>>(mod, c0, out);
}